// round 6
// baseline (speedup 1.0000x reference)
#include <cuda_runtime.h>
#include <cuda_bf16.h>

// Problem constants (fixed by the reference setup_inputs)
#define BB 64
#define SS 512
#define HH 768
#define WW 256      // MAX_WORD_LEN
#define WE 300
#define OUTW (HH + WE)   // 1068 floats = 267 float4
#define HV  (HH/4)       // 192 float4
#define WV  (WE/4)       // 75 float4
#define G   4            // words per CTA

// One CTA per (batch, group of 4 consecutive words). token_ids sorted per batch
// => segments of the 4 words are contiguous. Stage token_ids to smem once
// (amortized over 4 words), binary-search the first bound, linearly advance the
// remaining 4 bounds (broadcast LDS). w2v gather rows for all 4 words are
// prefetched before the barrier to overlap their DRAM latency with staging.
__global__ __launch_bounds__(128)
void embeddings_fused_kernel(const float* __restrict__ hidden,
                             const float* __restrict__ w2v,
                             const int*   __restrict__ token_ids,
                             const int*   __restrict__ word_ids,
                             float*       __restrict__ out)
{
    const int gidx = blockIdx.x;            // 0 .. B*W/G - 1   (4096)
    const int b    = gidx >> 6;             // / (WW/G)
    const int w0   = (gidx & 63) << 2;      // first word of the group
    const int tid  = threadIdx.x;

    __shared__ int st[SS];

    // ---- prefetch the 4 word ids (one aligned int4) + their w2v rows ----
    const int wbase = b * WW + w0;
    const int4 wids = __ldg(reinterpret_cast<const int4*>(word_ids + wbase));
    float4 g[G];
    if (tid < WV) {
        g[0] = __ldg(reinterpret_cast<const float4*>(w2v + (size_t)wids.x * WE) + tid);
        g[1] = __ldg(reinterpret_cast<const float4*>(w2v + (size_t)wids.y * WE) + tid);
        g[2] = __ldg(reinterpret_cast<const float4*>(w2v + (size_t)wids.z * WE) + tid);
        g[3] = __ldg(reinterpret_cast<const float4*>(w2v + (size_t)wids.w * WE) + tid);
    }

    // ---- stage token_ids (one LDG.128 per thread) ----
    reinterpret_cast<int4*>(st)[tid] =
        __ldg(reinterpret_cast<const int4*>(token_ids + b * SS) + tid);
    __syncthreads();

    // ---- bounds: binary search for lower_bound(w0), linear advance after.
    //      Every thread does the same work; all LDS are broadcast. ----
    int bnd[G + 1];
    {
        int lo = 0, hi = SS;
        while (lo < hi) {
            int m = (lo + hi) >> 1;
            if (st[m] < w0) lo = m + 1; else hi = m;
        }
        bnd[0] = lo;
        int s = lo;
        #pragma unroll
        for (int i = 1; i <= G; ++i) {
            const int tgt = w0 + i;
            while (s < SS && st[s] < tgt) ++s;
            bnd[i] = s;
        }
    }

    const float4* hbase = reinterpret_cast<const float4*>(hidden + (size_t)b * SS * HH);
    const bool has2 = (tid < (HV - 128));   // tid < 64

    #pragma unroll
    for (int i = 0; i < G; ++i) {
        const int lo  = bnd[i];
        const int cnt = bnd[i + 1] - lo;
        const float inv = (cnt > 0) ? (1.0f / (float)cnt) : 0.0f;

        float4 a0 = make_float4(0.f, 0.f, 0.f, 0.f);
        float4 a1 = make_float4(0.f, 0.f, 0.f, 0.f);
        const float4* r = hbase + (size_t)lo * HV;
        #pragma unroll 1
        for (int s = 0; s < cnt; ++s, r += HV) {
            float4 v0 = __ldcs(&r[tid]);
            a0.x += v0.x; a0.y += v0.y; a0.z += v0.z; a0.w += v0.w;
            if (has2) {
                float4 v1 = __ldcs(&r[tid + 128]);
                a1.x += v1.x; a1.y += v1.y; a1.z += v1.z; a1.w += v1.w;
            }
        }

        float4* orow = reinterpret_cast<float4*>(out + (size_t)(wbase + i) * OUTW);
        a0.x *= inv; a0.y *= inv; a0.z *= inv; a0.w *= inv;
        __stcs(&orow[tid], a0);
        if (has2) {
            a1.x *= inv; a1.y *= inv; a1.z *= inv; a1.w *= inv;
            __stcs(&orow[tid + 128], a1);
        }
        if (tid < WV) {
            __stcs(&orow[HV + tid], g[i]);
        }
    }
}

extern "C" void kernel_launch(void* const* d_in, const int* in_sizes, int n_in,
                              void* d_out, int out_size)
{
    // Identify inputs by element count (robust to ordering):
    //   hidden    : 64*512*768  = 25,165,824 (float32)
    //   w2v_table : 50000*300   = 15,000,000 (float32)
    //   token_ids : 64*512      = 32,768     (int32)
    //   word_ids  : 64*256      = 16,384     (int32)
    const float* hidden = nullptr;
    const float* w2v    = nullptr;
    const int*   tok    = nullptr;
    const int*   wids   = nullptr;
    for (int i = 0; i < n_in; ++i) {
        switch (in_sizes[i]) {
            case 25165824: hidden = (const float*)d_in[i]; break;
            case 15000000: w2v    = (const float*)d_in[i]; break;
            case 32768:    tok    = (const int*)d_in[i];   break;
            case 16384:    wids   = (const int*)d_in[i];   break;
            default: break;
        }
    }
    float* out = (float*)d_out;

    dim3 grid(BB * WW / G);   // 4096 CTAs
    dim3 block(128);
    embeddings_fused_kernel<<<grid, block>>>(hidden, w2v, tok, wids, out);
}

// round 8
// speedup vs baseline: 1.0094x; 1.0094x over previous
#include <cuda_runtime.h>
#include <cuda_bf16.h>

// Problem constants (fixed by the reference setup_inputs)
#define BB 64
#define SS 512
#define HH 768
#define WW 256      // MAX_WORD_LEN
#define WE 300
#define OUTW (HH + WE)   // 1068 floats = 267 float4
#define HV  (HH/4)       // 192 float4
#define WV  (WE/4)       // 75 float4

// Per-(batch,word) segment bounds, computed once by the bounds kernel.
// {x=lo, y=cnt}. 16384 * 8B = 128 KB device scratch (static, no allocation).
__device__ int2 g_bounds[BB * WW];

// ---- Kernel 1: one CTA per batch, 256 threads; thread w computes
//      lower_bound(w) over the batch's sorted token_ids (staged in smem),
//      then cnt[w] = lo[w+1] - lo[w] via a second smem pass. ----
__global__ __launch_bounds__(256)
void bounds_kernel(const int* __restrict__ token_ids)
{
    const int b   = blockIdx.x;
    const int tid = threadIdx.x;   // == word index w

    __shared__ int st[SS];
    __shared__ int slo[WW + 1];

    reinterpret_cast<int2*>(st)[tid] =
        __ldg(reinterpret_cast<const int2*>(token_ids + b * SS) + tid);
    __syncthreads();

    // lower_bound(tid) in st[0..512)
    int lo = 0, hi = SS;
    while (lo < hi) {
        int m = (lo + hi) >> 1;
        if (st[m] < tid) lo = m + 1; else hi = m;
    }
    slo[tid] = lo;
    if (tid == 0) slo[WW] = SS;    // all token ids < WW
    __syncthreads();

    g_bounds[b * WW + tid] = make_int2(lo, slo[tid + 1] - lo);
}

// ---- Kernel 2: one CTA per (batch, word); no smem, no barrier, no search.
//      Broadcast-load {lo,cnt}, mean-reduce the contiguous segment (dual
//      accumulator chains), gather the w2v row, write the concat row. ----
__global__ __launch_bounds__(128)
void embeddings_main_kernel(const float* __restrict__ hidden,
                            const float* __restrict__ w2v,
                            const int*   __restrict__ word_ids,
                            float*       __restrict__ out)
{
    const int bw  = blockIdx.x;        // 0 .. B*W-1
    const int b   = bw >> 8;
    const int tid = threadIdx.x;

    // Broadcast loads (same address warp-wide -> one sector each).
    const int2 lc  = __ldg(&g_bounds[bw]);
    const int  wid = __ldg(&word_ids[bw]);

    const int lo  = lc.x;
    const int cnt = lc.y;
    const float inv = (cnt > 0) ? (1.0f / (float)cnt) : 0.0f;

    float4* orow = reinterpret_cast<float4*>(out + (size_t)bw * OUTW);

    // Start the random gather early to overlap its latency with the reduction.
    float4 gv;
    const bool hasw = (tid < WV);
    if (hasw) {
        gv = __ldg(reinterpret_cast<const float4*>(w2v + (size_t)wid * WE) + tid);
    }

    // transformer mean: 192 float4 over 128 threads (tid, and tid+128 for tid<64)
    const float4* r = reinterpret_cast<const float4*>(hidden + (size_t)b * SS * HH)
                      + (size_t)lo * HV;
    const bool has2 = (tid < (HV - 128));   // tid < 64
    float4 a0 = make_float4(0.f, 0.f, 0.f, 0.f);
    float4 a1 = make_float4(0.f, 0.f, 0.f, 0.f);
    #pragma unroll 1
    for (int s = 0; s < cnt; ++s, r += HV) {
        float4 v0 = __ldcs(&r[tid]);
        a0.x += v0.x; a0.y += v0.y; a0.z += v0.z; a0.w += v0.w;
        if (has2) {
            float4 v1 = __ldcs(&r[tid + 128]);
            a1.x += v1.x; a1.y += v1.y; a1.z += v1.z; a1.w += v1.w;
        }
    }
    a0.x *= inv; a0.y *= inv; a0.z *= inv; a0.w *= inv;
    __stcs(&orow[tid], a0);
    if (has2) {
        a1.x *= inv; a1.y *= inv; a1.z *= inv; a1.w *= inv;
        __stcs(&orow[tid + 128], a1);
    }
    if (hasw) {
        __stcs(&orow[HV + tid], gv);
    }
}

extern "C" void kernel_launch(void* const* d_in, const int* in_sizes, int n_in,
                              void* d_out, int out_size)
{
    // Identify inputs by element count (robust to ordering):
    //   hidden    : 64*512*768  = 25,165,824 (float32)
    //   w2v_table : 50000*300   = 15,000,000 (float32)
    //   token_ids : 64*512      = 32,768     (int32)
    //   word_ids  : 64*256      = 16,384     (int32)
    const float* hidden = nullptr;
    const float* w2v    = nullptr;
    const int*   tok    = nullptr;
    const int*   wids   = nullptr;
    for (int i = 0; i < n_in; ++i) {
        switch (in_sizes[i]) {
            case 25165824: hidden = (const float*)d_in[i]; break;
            case 15000000: w2v    = (const float*)d_in[i]; break;
            case 32768:    tok    = (const int*)d_in[i];   break;
            case 16384:    wids   = (const int*)d_in[i];   break;
            default: break;
        }
    }
    float* out = (float*)d_out;

    bounds_kernel<<<BB, 256>>>(tok);                       // 64 CTAs, ~2 us
    embeddings_main_kernel<<<BB * WW, 128>>>(hidden, w2v, wids, out);
}